// round 8
// baseline (speedup 1.0000x reference)
#include <cuda_runtime.h>
#include <math.h>
#include <stdint.h>

#define NN 2000
#define BB 64
#define EMBED 512
#define LABELS 20
#define NC 31            // Taylor degree 30
typedef unsigned long long u64;

#define SPLIT0 7
#define CSPLIT0 18       // chunks (of k=16) per gemm0 split: 6x18 + 17 = 125
#define SPLIT1 16
#define CSPLIT1 8        // 15x8 + 5 = 125

// ---- scratch ----
__device__ float g_mixed[BB * NN];          // [b][n]
__device__ float g_part1[SPLIT0 * NN * BB];
__device__ float g_part2[SPLIT1 * EMBED * BB];
__device__ float g_hT[EMBED * BB];
__device__ float g_cn[NC][BB];
__device__ float g_cd[NC][BB];
__device__ float g_alpha, g_gamma;

__device__ __forceinline__ u64 pk2(float a, float b) {
    u64 r; asm("mov.b64 %0,{%1,%2};" : "=l"(r) : "f"(a), "f"(b)); return r;
}
__device__ __forceinline__ void fma2(u64& d, u64 a, u64 b) {
    asm("fma.rn.f32x2 %0,%1,%2,%0;" : "+l"(d) : "l"(a), "l"(b));
}

// ============================================================================
// Shared f32x2 GEMM: 64x64 tile, K chunks of 16, double-buffered smem.
// A [nrows x NN] row-major; X [64 x NN] row-major (row = output column b).
// dst partial buffer [sp][row][b]. Extra blocks (>= gemmBlocks) do moments.
// ============================================================================
__global__ __launch_bounds__(256) void k_gemm(
    const float* __restrict__ A, const float* __restrict__ Xin,
    int dstSel, int xSel, int nrows, int mtiles, int csplit, int gemmBlocks,
    const float* __restrict__ tw, const float* __restrict__ tb,
    const float* __restrict__ pw, int doMoments)
{
    const int bid = blockIdx.x, tid = threadIdx.x;
    if (bid < gemmBlocks) {
        __shared__ __align__(16) float sA[2][16][68];
        __shared__ __align__(16) float sX[2][16][68];
        float* dst = dstSel ? g_part2 : g_part1;
        const float* X = xSel ? (const float*)g_mixed : Xin;
        const int mt = bid % mtiles, sp = bid / mtiles;
        const int rb = mt * 64;
        const int c0 = sp * csplit;
        int nch = 125 - c0; if (nch > csplit) nch = csplit;
        const int m = tid >> 2, q = tid & 3;
        const int tx = tid & 15, ty = tid >> 4;
        const bool rok = (rb + m) < nrows;
        const float* arow = A + (size_t)(rb + m) * NN;
        const float* xrow = X + (size_t)m * NN;

        u64 acc[4][2];
#pragma unroll
        for (int i = 0; i < 4; i++) { acc[i][0] = 0ull; acc[i][1] = 0ull; }

        float4 pa, px;
        auto ldg = [&](int c) {
            int k = (c0 + c) * 16 + q * 4;
            pa = rok ? *(const float4*)(arow + k) : make_float4(0.f, 0.f, 0.f, 0.f);
            px = *(const float4*)(xrow + k);
        };
        auto sts = [&](int buf) {
            sA[buf][q * 4 + 0][m] = pa.x; sA[buf][q * 4 + 1][m] = pa.y;
            sA[buf][q * 4 + 2][m] = pa.z; sA[buf][q * 4 + 3][m] = pa.w;
            sX[buf][q * 4 + 0][m] = px.x; sX[buf][q * 4 + 1][m] = px.y;
            sX[buf][q * 4 + 2][m] = px.z; sX[buf][q * 4 + 3][m] = px.w;
        };

        ldg(0); sts(0); __syncthreads();
        int buf = 0;
        for (int c = 0; c < nch; c++) {
            bool more = (c + 1 < nch);
            if (more) ldg(c + 1);
#pragma unroll
            for (int k = 0; k < 16; k++) {
                float4 av = *(const float4*)&sA[buf][k][ty * 4];
                ulonglong2 xv = *(const ulonglong2*)&sX[buf][k][tx * 4];
                u64 a0 = pk2(av.x, av.x), a1 = pk2(av.y, av.y);
                u64 a2 = pk2(av.z, av.z), a3 = pk2(av.w, av.w);
                fma2(acc[0][0], a0, xv.x); fma2(acc[0][1], a0, xv.y);
                fma2(acc[1][0], a1, xv.x); fma2(acc[1][1], a1, xv.y);
                fma2(acc[2][0], a2, xv.x); fma2(acc[2][1], a2, xv.y);
                fma2(acc[3][0], a3, xv.x); fma2(acc[3][1], a3, xv.y);
            }
            __syncthreads();
            if (more) { sts(buf ^ 1); __syncthreads(); buf ^= 1; }
        }

        float* dp = dst + (size_t)sp * nrows * BB;
#pragma unroll
        for (int i = 0; i < 4; i++) {
            int r = rb + ty * 4 + i;
            if (r < nrows)
                *(ulonglong2*)(dp + (size_t)r * BB + tx * 4) =
                    make_ulonglong2(acc[i][0], acc[i][1]);
        }
        return;
    }

    if (!doMoments) return;
    // ---------------- moments (+ alpha/gamma on first block) ----------------
    const int b = bid - gemmBlocks;          // 0..63
    if (b == 0) {
        __shared__ float sa[64], sg[64];
        if (tid < 64) { sa[tid] = tw[tid] * pw[tid]; sg[tid] = tb[tid] * pw[tid]; }
        __syncthreads();
        if (tid == 0) {
            float Aa = 0.f, G = 0.f;
            for (int i = 0; i < 64; i++) { Aa += sa[i]; G += sg[i]; }
            g_alpha = Aa; g_gamma = G;
        }
        __syncthreads();
    }
    const float* xr = Xin + (size_t)b * NN;
    float acc[32];
#pragma unroll
    for (int k = 0; k < 32; k++) acc[k] = 0.f;
    for (int mm = tid; mm < NN; mm += 256) {
        float v = xr[mm];
        float p = 1.f;
#pragma unroll
        for (int k = 0; k < 32; k++) { acc[k] += p; p *= v; }
    }
#pragma unroll
    for (int k = 0; k < 32; k++) {
#pragma unroll
        for (int off = 16; off > 0; off >>= 1)
            acc[k] += __shfl_down_sync(0xffffffffu, acc[k], off);
    }
    __shared__ float red[32][8];
    __shared__ float sM[32];
    int lane = tid & 31, warp = tid >> 5;
    if (lane == 0) {
#pragma unroll
        for (int k = 0; k < 32; k++) red[k][warp] = acc[k];
    }
    __syncthreads();
    if (tid < 32) {
        float s = 0.f;
        for (int w = 0; w < 8; w++) s += red[tid][w];
        sM[tid] = s;
    }
    __syncthreads();
    if (tid < NC) {
        int k = tid;
        float fact = 1.f;
        for (int i = 2; i <= k; i++) fact *= (float)i;
        g_cd[k][b] = sM[k] / fact;
        g_cn[k][b] = sM[k + 1] / fact;
    }
}

// ============================================================================
// mix: reduce 7 partials + exact softmax term g(s) + relu + residual
//      -> g_mixed[b][n] (b-major so gemm1 can consume it as X)
// ============================================================================
__global__ __launch_bounds__(256) void k_mix(const float* __restrict__ feat) {
    __shared__ float xs[64][17];
    __shared__ float ms[16][68];
    const int tid = threadIdx.x;
    const int n0 = blockIdx.x * 16;          // 125 blocks
    {
        int bl = tid >> 2, no = (tid & 3) * 4;
        float4 v = *(const float4*)(feat + (size_t)bl * NN + n0 + no);
        xs[bl][no] = v.x; xs[bl][no + 1] = v.y;
        xs[bl][no + 2] = v.z; xs[bl][no + 3] = v.w;
    }
    __syncthreads();
    {
        int nl = tid >> 4, b4 = (tid & 15) * 4;
        size_t row = (size_t)(n0 + nl) * BB + b4;
        float4 pre = *(float4*)(g_part1 + row);
#pragma unroll
        for (int p = 1; p < SPLIT0; p++) {
            float4 v = *(float4*)(g_part1 + (size_t)p * NN * BB + row);
            pre.x += v.x; pre.y += v.y; pre.z += v.z; pre.w += v.w;
        }
        float al = g_alpha, ga = g_gamma;
        float xv0 = xs[b4 + 0][nl], xv1 = xs[b4 + 1][nl];
        float xv2 = xs[b4 + 2][nl], xv3 = xs[b4 + 3][nl];
        float s0 = al * xv0 + ga, s1 = al * xv1 + ga;
        float s2 = al * xv2 + ga, s3 = al * xv3 + ga;
        float4 P = *(float4*)&g_cn[NC - 1][b4];
        float4 Q = *(float4*)&g_cd[NC - 1][b4];
#pragma unroll
        for (int k = NC - 2; k >= 0; k--) {
            float4 cn = *(float4*)&g_cn[k][b4];
            float4 cd = *(float4*)&g_cd[k][b4];
            P.x = P.x * s0 + cn.x; Q.x = Q.x * s0 + cd.x;
            P.y = P.y * s1 + cn.y; Q.y = Q.y * s1 + cd.y;
            P.z = P.z * s2 + cn.z; Q.z = Q.z * s2 + cd.z;
            P.w = P.w * s3 + cn.w; Q.w = Q.w * s3 + cd.w;
        }
        float r0 = pre.x + P.x / Q.x, r1 = pre.y + P.y / Q.y;
        float r2 = pre.z + P.z / Q.z, r3 = pre.w + P.w / Q.w;
        ms[nl][b4 + 0] = (r0 > 0.f ? r0 : 0.f) + xv0;
        ms[nl][b4 + 1] = (r1 > 0.f ? r1 : 0.f) + xv1;
        ms[nl][b4 + 2] = (r2 > 0.f ? r2 : 0.f) + xv2;
        ms[nl][b4 + 3] = (r3 > 0.f ? r3 : 0.f) + xv3;
    }
    __syncthreads();
    {
        int bl = tid >> 2, no = (tid & 3) * 4;
        float4 v = make_float4(ms[no][bl], ms[no + 1][bl], ms[no + 2][bl], ms[no + 3][bl]);
        *(float4*)(g_mixed + (size_t)bl * NN + n0 + no) = v;
    }
}

// reduce 16 fc1 partials + bias + tanh -> hT[e][b]
__global__ __launch_bounds__(128) void k_hid(const float* __restrict__ b1) {
    int idx4 = (blockIdx.x * 128 + threadIdx.x) * 4;   // 64*128*4 == EMBED*BB
    int e = idx4 >> 6;
    float bb1 = b1[e];
    float4 s = make_float4(bb1, bb1, bb1, bb1);
#pragma unroll
    for (int p = 0; p < SPLIT1; p++) {
        float4 v = *(float4*)(g_part2 + (size_t)p * EMBED * BB + idx4);
        s.x += v.x; s.y += v.y; s.z += v.z; s.w += v.w;
    }
    float4 h;
    h.x = tanhf(s.x); h.y = tanhf(s.y); h.z = tanhf(s.z); h.w = tanhf(s.w);
    *(float4*)(g_hT + idx4) = h;
}

// logits[b][l] = sum_e w2[l][e] * hT[e][b] + b2[l]
__global__ void k_logits(const float* __restrict__ w2, const float* __restrict__ b2,
                         float* __restrict__ out) {
    int l = blockIdx.x;
    int t = threadIdx.x;
    int b = t & 63, qq = t >> 6;
    const float* wr = w2 + l * EMBED + qq * 128;
    const float* hp = g_hT + (qq * 128) * BB + b;
    float acc = 0.f;
#pragma unroll 8
    for (int e = 0; e < 128; e++) acc += wr[e] * hp[e * BB];
    __shared__ float s[256];
    s[t] = acc;
    __syncthreads();
    if (qq == 0)
        out[b * LABELS + l] = s[b] + s[64 + b] + s[128 + b] + s[192 + b] + b2[l];
}

extern "C" void kernel_launch(void* const* d_in, const int* in_sizes, int n_in,
                              void* d_out, int out_size) {
    const float* feature    = (const float*)d_in[0];
    const float* init_graph = (const float*)d_in[1];
    const float* theta_w    = (const float*)d_in[2];
    const float* theta_b    = (const float*)d_in[3];
    const float* phi_w      = (const float*)d_in[4];
    /* phi_b cancels in the softmax */
    const float* fc1_w      = (const float*)d_in[6];
    const float* fc1_b      = (const float*)d_in[7];
    const float* fc2_w      = (const float*)d_in[8];
    const float* fc2_b      = (const float*)d_in[9];
    float* out = (float*)d_out;

    // gemm0: 32 mtiles x 7 splits = 224 gemm blocks + 64 moments blocks
    k_gemm<<<288, 256>>>(init_graph, feature, /*dstSel=*/0, /*xSel=*/0,
                         NN, 32, CSPLIT0, 224, theta_w, theta_b, phi_w, 1);
    k_mix<<<125, 256>>>(feature);
    // gemm1 (fc1): 8 mtiles x 16 splits = 128 blocks
    k_gemm<<<128, 256>>>(fc1_w, nullptr, /*dstSel=*/1, /*xSel=*/1,
                         EMBED, 8, CSPLIT1, 128, nullptr, nullptr, nullptr, 0);
    k_hid<<<64, 128>>>(fc1_b);
    k_logits<<<LABELS, 256>>>(fc2_w, fc2_b, out);
}

// round 10
// speedup vs baseline: 1.1963x; 1.1963x over previous
#include <cuda_runtime.h>
#include <cuda_bf16.h>
#include <math.h>
#include <stdint.h>

#define NN 2000
#define BB 64
#define EMBED 512
#define LABELS 20
#define NC 31            // Taylor degree 30

#define SPLIT0 4
#define SPLIT1 16

// smem per gemm buffer: 4 tiles (Ahi,Alo,Bhi,Blo) of 64 rows x 72 bf16
#define A_PAD 72
#define TILEB (64 * A_PAD * 2)       // 9216
#define OFF_ALO TILEB
#define OFF_BHI (2 * TILEB)
#define OFF_BLO (3 * TILEB)
#define BUF_STRIDE (4 * TILEB)       // 36864
#define DSMEM (2 * BUF_STRIDE)       // 73728

// ---- scratch ----
__device__ float g_mixed[BB * NN];          // [b][n]
__device__ float g_part1[SPLIT0 * NN * BB]; // [sp][n][b]
__device__ float g_part2[SPLIT1 * EMBED * BB];
__device__ float g_hT[EMBED * BB];          // [e][b]
__device__ float g_cn[NC][BB];
__device__ float g_cd[NC][BB];
__device__ float g_alpha, g_gamma;

__device__ __forceinline__ void mma16816(float* d, const uint32_t* a, const uint32_t* b) {
    asm volatile(
        "mma.sync.aligned.m16n8k16.row.col.f32.bf16.bf16.f32 "
        "{%0,%1,%2,%3}, {%4,%5,%6,%7}, {%8,%9}, {%0,%1,%2,%3};\n"
        : "+f"(d[0]), "+f"(d[1]), "+f"(d[2]), "+f"(d[3])
        : "r"(a[0]), "r"(a[1]), "r"(a[2]), "r"(a[3]), "r"(b[0]), "r"(b[1]));
}

__device__ __forceinline__ void split_store(char* hi, char* lo, int byte, float4 v) {
    __nv_bfloat16 hx = __float2bfloat16(v.x), hy = __float2bfloat16(v.y);
    __nv_bfloat16 hz = __float2bfloat16(v.z), hw = __float2bfloat16(v.w);
    float lx = v.x - __bfloat162float(hx), ly = v.y - __bfloat162float(hy);
    float lz = v.z - __bfloat162float(hz), lw = v.w - __bfloat162float(hw);
    uint2 h2, l2;
    h2.x = (unsigned)__bfloat16_as_ushort(hx) | ((unsigned)__bfloat16_as_ushort(hy) << 16);
    h2.y = (unsigned)__bfloat16_as_ushort(hz) | ((unsigned)__bfloat16_as_ushort(hw) << 16);
    __nv_bfloat16 ax = __float2bfloat16(lx), ay = __float2bfloat16(ly);
    __nv_bfloat16 az = __float2bfloat16(lz), aw = __float2bfloat16(lw);
    l2.x = (unsigned)__bfloat16_as_ushort(ax) | ((unsigned)__bfloat16_as_ushort(ay) << 16);
    l2.y = (unsigned)__bfloat16_as_ushort(az) | ((unsigned)__bfloat16_as_ushort(aw) << 16);
    *(uint2*)(hi + byte) = h2;
    *(uint2*)(lo + byte) = l2;
}

// 64x64 output tile, K window [kb,ke) in chunks of 64, bf16-split 3-mma, fp32 acc.
// A: [nrows x NN] row-major. Bmat: 64 rows x NN row-major (row = output col b).
// dst: partial buffer [row][b], rows guarded by nrows.  (verified in R7)
__device__ __forceinline__ void gemm_tile(
    const float* __restrict__ A, const float* __restrict__ Bmat,
    float* __restrict__ dst, int nrows, int rb, int kb, int ke,
    char* dsm, int tid)
{
    const int wid = tid >> 5, lane = tid & 31;
    const int warp_m = wid >> 2, warp_n = wid & 3;
    const int g = lane >> 2, tig = lane & 3;
    const int rr = tid >> 2;
    const int q4 = (tid & 3) * 16;
    const bool rok = (rb + rr) < nrows;
    const float* arow = A + (size_t)(rb + rr) * NN;
    const float* brow = Bmat + (size_t)rr * NN;
    const int nc = (ke - kb + 63) >> 6;

    float acc[2][2][4];
#pragma unroll
    for (int t = 0; t < 2; t++)
#pragma unroll
        for (int u = 0; u < 2; u++)
#pragma unroll
            for (int j = 0; j < 4; j++) acc[t][u][j] = 0.f;

    float4 ra[4], rbv[4];
    auto ldg_chunk = [&](int c) {
        int m0 = kb + c * 64;
        int mlen = ke - m0; if (mlen > 64) mlen = 64;
#pragma unroll
        for (int i = 0; i < 4; i++) {
            int kk = q4 + i * 4;
            bool ok = (kk + 4 <= mlen);
            ra[i] = (rok && ok) ? *(const float4*)(arow + m0 + kk)
                                : make_float4(0.f, 0.f, 0.f, 0.f);
            rbv[i] = ok ? *(const float4*)(brow + m0 + kk)
                        : make_float4(0.f, 0.f, 0.f, 0.f);
        }
    };
    auto cvt_store = [&](int p) {
        char* base = dsm + p * BUF_STRIDE;
#pragma unroll
        for (int i = 0; i < 4; i++) {
            int kk = q4 + i * 4;
            split_store(base, base + OFF_ALO, rr * (A_PAD * 2) + kk * 2, ra[i]);
            split_store(base + OFF_BHI, base + OFF_BLO, rr * (A_PAD * 2) + kk * 2, rbv[i]);
        }
    };
    auto compute = [&](int p) {
        char* base = dsm + p * BUF_STRIDE;
        char* Ahi = base;            char* Alo = base + OFF_ALO;
        char* Bhi = base + OFF_BHI;  char* Blo = base + OFF_BLO;
#pragma unroll
        for (int ks = 0; ks < 4; ks++) {
            const int ko = ks * 16;
            uint32_t ah[2][4], al[2][4], bh[2][2], bl[2][2];
#pragma unroll
            for (int t = 0; t < 2; t++) {
                int row = warp_m * 32 + t * 16 + g;
                int o0 = row * (A_PAD * 2) + (ko + tig * 2) * 2;
                int o1 = (row + 8) * (A_PAD * 2) + (ko + tig * 2) * 2;
                ah[t][0] = *(uint32_t*)(Ahi + o0);
                ah[t][1] = *(uint32_t*)(Ahi + o1);
                ah[t][2] = *(uint32_t*)(Ahi + o0 + 16);
                ah[t][3] = *(uint32_t*)(Ahi + o1 + 16);
                al[t][0] = *(uint32_t*)(Alo + o0);
                al[t][1] = *(uint32_t*)(Alo + o1);
                al[t][2] = *(uint32_t*)(Alo + o0 + 16);
                al[t][3] = *(uint32_t*)(Alo + o1 + 16);
            }
#pragma unroll
            for (int u = 0; u < 2; u++) {
                int col = warp_n * 16 + u * 8 + g;
                int o = col * (A_PAD * 2) + (ko + tig * 2) * 2;
                bh[u][0] = *(uint32_t*)(Bhi + o);
                bh[u][1] = *(uint32_t*)(Bhi + o + 16);
                bl[u][0] = *(uint32_t*)(Blo + o);
                bl[u][1] = *(uint32_t*)(Blo + o + 16);
            }
#pragma unroll
            for (int t = 0; t < 2; t++)
#pragma unroll
                for (int u = 0; u < 2; u++) {
                    mma16816(acc[t][u], ah[t], bh[u]);
                    mma16816(acc[t][u], ah[t], bl[u]);
                    mma16816(acc[t][u], al[t], bh[u]);
                }
        }
    };

    ldg_chunk(0);
    for (int c = 0; c < nc; c++) {
        int p = c & 1;
        cvt_store(p);
        if (c + 1 < nc) ldg_chunk(c + 1);
        __syncthreads();
        compute(p);
    }

#pragma unroll
    for (int t = 0; t < 2; t++) {
        int r0 = rb + warp_m * 32 + t * 16 + g;
#pragma unroll
        for (int u = 0; u < 2; u++) {
            int cn = warp_n * 16 + u * 8 + tig * 2;
            if (r0 < nrows)
                *(float2*)(dst + (size_t)r0 * BB + cn) = make_float2(acc[t][u][0], acc[t][u][1]);
            if (r0 + 8 < nrows)
                *(float2*)(dst + (size_t)(r0 + 8) * BB + cn) = make_float2(acc[t][u][2], acc[t][u][3]);
        }
    }
}

// ============ gemm0 (blocks 0..127) + moments (128..143): one wave ==========
__global__ __launch_bounds__(256, 1)
void k_main(const float* __restrict__ IG, const float* __restrict__ feat,
            const float* __restrict__ tw, const float* __restrict__ tb,
            const float* __restrict__ pw)
{
    extern __shared__ __align__(16) char dsm[];
    const int bid = blockIdx.x, tid = threadIdx.x;
    if (bid < 128) {
        int mt = bid & 31, sp = bid >> 5;
        int kb = sp * 500, ke = kb + 500;
        gemm_tile(IG, feat, g_part1 + (size_t)sp * NN * BB, NN, mt * 64, kb, ke, dsm, tid);
        return;
    }
    // moments: blocks 128..143, 4 batches each
    if (bid == 128) {
        __shared__ float sa[64], sg[64];
        if (tid < 64) { sa[tid] = tw[tid] * pw[tid]; sg[tid] = tb[tid] * pw[tid]; }
        __syncthreads();
        if (tid == 0) {
            float A = 0.f, G = 0.f;
            for (int i = 0; i < 64; i++) { A += sa[i]; G += sg[i]; }
            g_alpha = A; g_gamma = G;
        }
        __syncthreads();
    }
    __shared__ float red[32][8];
    __shared__ float sM[32];
    for (int ib = 0; ib < 4; ib++) {
        int b = (bid - 128) * 4 + ib;
        const float* xr = feat + (size_t)b * NN;
        float acc[32];
#pragma unroll
        for (int k = 0; k < 32; k++) acc[k] = 0.f;
        for (int m = tid; m < NN; m += 256) {
            float v = xr[m];
            float p = 1.f;
#pragma unroll
            for (int k = 0; k < 32; k++) { acc[k] += p; p *= v; }
        }
#pragma unroll
        for (int k = 0; k < 32; k++) {
#pragma unroll
            for (int off = 16; off > 0; off >>= 1)
                acc[k] += __shfl_down_sync(0xffffffffu, acc[k], off);
        }
        int lane = tid & 31, warp = tid >> 5;
        if (lane == 0) {
#pragma unroll
            for (int k = 0; k < 32; k++) red[k][warp] = acc[k];
        }
        __syncthreads();
        if (tid < 32) {
            float s = 0.f;
            for (int w = 0; w < 8; w++) s += red[tid][w];
            sM[tid] = s;
        }
        __syncthreads();
        if (tid < NC) {
            int k = tid;
            float fact = 1.f;
            for (int i = 2; i <= k; i++) fact *= (float)i;
            g_cd[k][b] = sM[k] / fact;
            g_cn[k][b] = sM[k + 1] / fact;
        }
        __syncthreads();
    }
}

// ====== mix: partials + exact softmax term + relu + residual -> mixed[b][n] ==
__global__ __launch_bounds__(256) void k_mix(const float* __restrict__ feat) {
    __shared__ float xs[64][17];
    __shared__ float ms[16][68];
    const int tid = threadIdx.x;
    const int n0 = blockIdx.x * 16;          // 125 blocks
    {
        int bl = tid >> 2, no = (tid & 3) * 4;
        float4 v = *(const float4*)(feat + (size_t)bl * NN + n0 + no);
        xs[bl][no] = v.x; xs[bl][no + 1] = v.y;
        xs[bl][no + 2] = v.z; xs[bl][no + 3] = v.w;
    }
    __syncthreads();
    {
        int nl = tid >> 4, b4 = (tid & 15) * 4;
        size_t row = (size_t)(n0 + nl) * BB + b4;
        float4 pre = *(float4*)(g_part1 + row);
#pragma unroll
        for (int p = 1; p < SPLIT0; p++) {
            float4 v = *(float4*)(g_part1 + (size_t)p * NN * BB + row);
            pre.x += v.x; pre.y += v.y; pre.z += v.z; pre.w += v.w;
        }
        float al = g_alpha, ga = g_gamma;
        float xv0 = xs[b4 + 0][nl], xv1 = xs[b4 + 1][nl];
        float xv2 = xs[b4 + 2][nl], xv3 = xs[b4 + 3][nl];
        float s0 = al * xv0 + ga, s1 = al * xv1 + ga;
        float s2 = al * xv2 + ga, s3 = al * xv3 + ga;
        float4 P = *(float4*)&g_cn[NC - 1][b4];
        float4 Q = *(float4*)&g_cd[NC - 1][b4];
#pragma unroll
        for (int k = NC - 2; k >= 0; k--) {
            float4 cn = *(float4*)&g_cn[k][b4];
            float4 cd = *(float4*)&g_cd[k][b4];
            P.x = P.x * s0 + cn.x; Q.x = Q.x * s0 + cd.x;
            P.y = P.y * s1 + cn.y; Q.y = Q.y * s1 + cd.y;
            P.z = P.z * s2 + cn.z; Q.z = Q.z * s2 + cd.z;
            P.w = P.w * s3 + cn.w; Q.w = Q.w * s3 + cd.w;
        }
        float r0 = pre.x + P.x / Q.x, r1 = pre.y + P.y / Q.y;
        float r2 = pre.z + P.z / Q.z, r3 = pre.w + P.w / Q.w;
        ms[nl][b4 + 0] = (r0 > 0.f ? r0 : 0.f) + xv0;
        ms[nl][b4 + 1] = (r1 > 0.f ? r1 : 0.f) + xv1;
        ms[nl][b4 + 2] = (r2 > 0.f ? r2 : 0.f) + xv2;
        ms[nl][b4 + 3] = (r3 > 0.f ? r3 : 0.f) + xv3;
    }
    __syncthreads();
    {
        int bl = tid >> 2, no = (tid & 3) * 4;
        float4 v = make_float4(ms[no][bl], ms[no + 1][bl], ms[no + 2][bl], ms[no + 3][bl]);
        *(float4*)(g_mixed + (size_t)bl * NN + n0 + no) = v;
    }
}

// ================= fc1 GEMM: 8 mtiles x 16 splits = 128 blocks ===============
__global__ __launch_bounds__(256, 1)
void k_gemm1(const float* __restrict__ w1) {
    extern __shared__ __align__(16) char dsm[];
    const int bid = blockIdx.x, tid = threadIdx.x;
    int mt = bid & 7, sp = bid >> 3;
    int kb = sp * 128, ke = kb + 128; if (ke > NN) ke = NN;
    gemm_tile(w1, g_mixed, g_part2 + (size_t)sp * EMBED * BB, EMBED, mt * 64, kb, ke, dsm, tid);
}

// ===== reduce 16 partials + bias + fast tanh (2 MUFU) -> hT[e][b] ============
// 32 blocks * 256 threads * 4 elems = 32768 == EMBED*BB exactly.
__global__ __launch_bounds__(256) void k_hid(const float* __restrict__ b1) {
    int idx4 = (blockIdx.x * 256 + threadIdx.x) * 4;
    int e = idx4 >> 6;
    float bb1 = b1[e];
    float4 s = make_float4(bb1, bb1, bb1, bb1);
#pragma unroll
    for (int p = 0; p < SPLIT1; p++) {
        float4 v = *(float4*)(g_part2 + (size_t)p * EMBED * BB + idx4);
        s.x += v.x; s.y += v.y; s.z += v.z; s.w += v.w;
    }
    float4 h;
    h.x = 1.f - __fdividef(2.f, __expf(2.f * s.x) + 1.f);
    h.y = 1.f - __fdividef(2.f, __expf(2.f * s.y) + 1.f);
    h.z = 1.f - __fdividef(2.f, __expf(2.f * s.z) + 1.f);
    h.w = 1.f - __fdividef(2.f, __expf(2.f * s.w) + 1.f);
    *(float4*)(g_hT + idx4) = h;
}

// logits[b][l] = sum_e w2[l][e] * hT[e][b] + b2[l]
__global__ void k_logits(const float* __restrict__ w2, const float* __restrict__ b2,
                         float* __restrict__ out) {
    int l = blockIdx.x;
    int t = threadIdx.x;
    int b = t & 63, qq = t >> 6;
    const float* wr = w2 + l * EMBED + qq * 128;
    const float* hp = g_hT + (qq * 128) * BB + b;
    float acc = 0.f;
#pragma unroll 8
    for (int e = 0; e < 128; e++) acc += wr[e] * hp[e * BB];
    __shared__ float s[256];
    s[t] = acc;
    __syncthreads();
    if (qq == 0)
        out[b * LABELS + l] = s[b] + s[64 + b] + s[128 + b] + s[192 + b] + b2[l];
}

extern "C" void kernel_launch(void* const* d_in, const int* in_sizes, int n_in,
                              void* d_out, int out_size) {
    const float* feature    = (const float*)d_in[0];
    const float* init_graph = (const float*)d_in[1];
    const float* theta_w    = (const float*)d_in[2];
    const float* theta_b    = (const float*)d_in[3];
    const float* phi_w      = (const float*)d_in[4];
    /* phi_b cancels in the softmax */
    const float* fc1_w      = (const float*)d_in[6];
    const float* fc1_b      = (const float*)d_in[7];
    const float* fc2_w      = (const float*)d_in[8];
    const float* fc2_b      = (const float*)d_in[9];
    float* out = (float*)d_out;

    cudaFuncSetAttribute(k_main, cudaFuncAttributeMaxDynamicSharedMemorySize, DSMEM);
    cudaFuncSetAttribute(k_gemm1, cudaFuncAttributeMaxDynamicSharedMemorySize, DSMEM);

    k_main<<<144, 256, DSMEM>>>(init_graph, feature, theta_w, theta_b, phi_w);
    k_mix<<<125, 256>>>(feature);
    k_gemm1<<<128, 256, DSMEM>>>(fc1_w);
    k_hid<<<32, 256>>>(fc1_b);
    k_logits<<<LABELS, 256>>>(fc2_w, fc2_b, out);
}